// round 2
// baseline (speedup 1.0000x reference)
#include <cuda_runtime.h>
#include <cuda_bf16.h>

#define BB 64
#define TT 288
#define VV 24
#define DD 256
#define NBT (BB * TT)
// TOD 128 | DOW 32 | DOM 32 | DOY 64

#define GRID_CTAS 296   // ~2 per SM on 148-SM sm_100a; grid-stride persistent

__global__ __launch_bounds__(256, 2) void input_embedding_kernel(
    const float* __restrict__ features,     // (B,T,V)
    const int*   __restrict__ bar_in_day,   // (B,T)
    const int*   __restrict__ day_of_week,  // (B,)
    const int*   __restrict__ day_of_month, // (B,)
    const int*   __restrict__ day_of_year,  // (B,)
    const float4* __restrict__ W,           // (V,D) as float4
    const float4* __restrict__ bias,        // (V,D) as float4
    const float* __restrict__ tod_table,    // (288,128)
    const float* __restrict__ dow_table,    // (7,32)
    const float* __restrict__ dom_table,    // (32,32)
    const float* __restrict__ doy_table,    // (367,64)
    float4* __restrict__ out)               // (B,T,V,D) as float4
{
    __shared__ __align__(16) float pos[DD];
    __shared__ float sx[VV];

    const int tid = threadIdx.x;
    const int d4  = tid & 63;        // constant float4 column per thread
    const int vb  = tid >> 6;        // 0..3; thread owns rows vb, vb+4, ..., vb+20

    // ---- preload this thread's W/bias working set into registers (once) ----
    float4 w[6], bv[6];
    #pragma unroll
    for (int k = 0; k < 6; k++) {
        const int v = vb + 4 * k;
        w[k]  = W[v * 64 + d4];
        bv[k] = bias[v * 64 + d4];
    }

    for (int bt = blockIdx.x; bt < NBT; bt += gridDim.x) {
        const int b = bt / TT;

        // ---- build composite positional vector pos[0..255] in smem ----
        if (tid < 128) {
            pos[tid] = tod_table[bar_in_day[bt] * 128 + tid];
        } else if (tid < 160) {
            pos[tid] = dow_table[day_of_week[b] * 32 + (tid - 128)];
        } else if (tid < 192) {
            pos[tid] = dom_table[day_of_month[b] * 32 + (tid - 160)];
        } else {
            pos[tid] = doy_table[day_of_year[b] * 64 + (tid - 192)];
        }
        if (tid < VV) sx[tid] = features[bt * VV + tid];
        __syncthreads();

        const float4 pp = reinterpret_cast<const float4*>(pos)[d4];
        float xs[6];
        #pragma unroll
        for (int k = 0; k < 6; k++) xs[k] = sx[vb + 4 * k];

        float4* __restrict__ outb = out + (size_t)bt * (VV * DD / 4);
        #pragma unroll
        for (int k = 0; k < 6; k++) {
            const int v = vb + 4 * k;
            float4 o;
            o.x = fmaf(xs[k], w[k].x, bv[k].x) + pp.x;
            o.y = fmaf(xs[k], w[k].y, bv[k].y) + pp.y;
            o.z = fmaf(xs[k], w[k].z, bv[k].z) + pp.z;
            o.w = fmaf(xs[k], w[k].w, bv[k].w) + pp.w;
            __stcs(&outb[v * 64 + d4], o);   // streaming store
        }
        __syncthreads();   // pos/sx reads done before next-iter overwrite
    }
}

extern "C" void kernel_launch(void* const* d_in, const int* in_sizes, int n_in,
                              void* d_out, int out_size) {
    const float* features     = (const float*)d_in[0];
    const int*   bar_in_day   = (const int*)d_in[1];
    const int*   day_of_week  = (const int*)d_in[2];
    const int*   day_of_month = (const int*)d_in[3];
    const int*   day_of_year  = (const int*)d_in[4];
    const float4* W           = (const float4*)d_in[5];
    const float4* bias        = (const float4*)d_in[6];
    const float* tod_table    = (const float*)d_in[7];
    const float* dow_table    = (const float*)d_in[8];
    const float* dom_table    = (const float*)d_in[9];
    const float* doy_table    = (const float*)d_in[10];
    float4* out = (float4*)d_out;

    input_embedding_kernel<<<GRID_CTAS, 256>>>(
        features, bar_in_day, day_of_week, day_of_month, day_of_year,
        W, bias, tod_table, dow_table, dom_table, doy_table, out);
}

// round 3
// speedup vs baseline: 1.0260x; 1.0260x over previous
#include <cuda_runtime.h>

#define BB 64
#define TT 288
#define VV 24
#define DD 256
#define NBT (BB * TT)
#define CHUNK 16                 // consecutive t per CTA (288 % 16 == 0 -> b fixed per CTA)
#define NCTA (NBT / CHUNK)       // 1152
// TOD 128 | DOW 32 | DOM 32 | DOY 64  (float4 cols: 0..31 | 32..39 | 40..47 | 48..63)

__global__ __launch_bounds__(768, 2) void input_embedding_kernel(
    const float* __restrict__ features,     // (B,T,V)
    const int*   __restrict__ bar_in_day,   // (B,T)
    const int*   __restrict__ day_of_week,  // (B,)
    const int*   __restrict__ day_of_month, // (B,)
    const int*   __restrict__ day_of_year,  // (B,)
    const float4* __restrict__ W,           // (V,D) as float4
    const float4* __restrict__ bias,        // (V,D) as float4
    const float4* __restrict__ tod_table,   // (288,32) float4
    const float4* __restrict__ dow_table,   // (7,8)    float4
    const float4* __restrict__ dom_table,   // (32,8)   float4
    const float4* __restrict__ doy_table,   // (367,16) float4
    float4* __restrict__ out)               // (B,T,V,D) as float4
{
    const int tid = threadIdx.x;
    const int d4  = tid & 63;        // float4 column, fixed per thread
    const int vb  = tid >> 6;        // 0..11; thread owns rows vb and vb+12

    const int bt0 = blockIdx.x * CHUNK;
    const int b   = bt0 / TT;        // constant for the whole CTA

    // ---- register-cache this thread's W/bias (reused over CHUNK iterations) ----
    const float4 w0  = W[vb * 64 + d4];
    const float4 w1  = W[(vb + 12) * 64 + d4];
    const float4 bv0 = bias[vb * 64 + d4];
    const float4 bv1 = bias[(vb + 12) * 64 + d4];

    // ---- positional float4: segment is fixed per thread ----
    // d4<32: tod (reloaded per t). Otherwise loop-invariant for this CTA.
    float4 pp;
    if (d4 >= 48)      pp = doy_table[day_of_year[b] * 16 + (d4 - 48)];
    else if (d4 >= 40) pp = dom_table[day_of_month[b] * 8 + (d4 - 40)];
    else if (d4 >= 32) pp = dow_table[day_of_week[b] * 8 + (d4 - 32)];

    const bool is_tod = (d4 < 32);

    #pragma unroll 4
    for (int i = 0; i < CHUNK; i++) {
        const int bt = bt0 + i;
        if (is_tod) pp = tod_table[bar_in_day[bt] * 32 + d4];   // even warps only

        const float x0 = features[bt * VV + vb];        // warp-uniform
        const float x1 = features[bt * VV + vb + 12];   // warp-uniform

        float4 o0, o1;
        o0.x = fmaf(x0, w0.x, bv0.x) + pp.x;
        o0.y = fmaf(x0, w0.y, bv0.y) + pp.y;
        o0.z = fmaf(x0, w0.z, bv0.z) + pp.z;
        o0.w = fmaf(x0, w0.w, bv0.w) + pp.w;
        o1.x = fmaf(x1, w1.x, bv1.x) + pp.x;
        o1.y = fmaf(x1, w1.y, bv1.y) + pp.y;
        o1.z = fmaf(x1, w1.z, bv1.z) + pp.z;
        o1.w = fmaf(x1, w1.w, bv1.w) + pp.w;

        float4* __restrict__ outb = out + (size_t)bt * (VV * DD / 4);
        __stcs(&outb[vb * 64 + d4], o0);
        __stcs(&outb[(vb + 12) * 64 + d4], o1);
    }
}

extern "C" void kernel_launch(void* const* d_in, const int* in_sizes, int n_in,
                              void* d_out, int out_size) {
    const float* features     = (const float*)d_in[0];
    const int*   bar_in_day   = (const int*)d_in[1];
    const int*   day_of_week  = (const int*)d_in[2];
    const int*   day_of_month = (const int*)d_in[3];
    const int*   day_of_year  = (const int*)d_in[4];
    const float4* W           = (const float4*)d_in[5];
    const float4* bias        = (const float4*)d_in[6];
    const float4* tod_table   = (const float4*)d_in[7];
    const float4* dow_table   = (const float4*)d_in[8];
    const float4* dom_table   = (const float4*)d_in[9];
    const float4* doy_table   = (const float4*)d_in[10];
    float4* out = (float4*)d_out;

    input_embedding_kernel<<<NCTA, 768>>>(
        features, bar_in_day, day_of_week, day_of_month, day_of_year,
        W, bias, tod_table, dow_table, dom_table, doy_table, out);
}

// round 4
// speedup vs baseline: 1.0882x; 1.0607x over previous
#include <cuda_runtime.h>
#include <cuda_bf16.h>

#define BB 64
#define TT 288
#define VV 24
#define DD 256
// TOD 128 | DOW 32 | DOM 32 | DOY 64

__global__ __launch_bounds__(256, 8) void input_embedding_kernel(
    const float* __restrict__ features,     // (B,T,V)
    const int*   __restrict__ bar_in_day,   // (B,T)
    const int*   __restrict__ day_of_week,  // (B,)
    const int*   __restrict__ day_of_month, // (B,)
    const int*   __restrict__ day_of_year,  // (B,)
    const float4* __restrict__ W,           // (V,D) as float4
    const float4* __restrict__ bias,        // (V,D) as float4
    const float* __restrict__ tod_table,    // (288,128)
    const float* __restrict__ dow_table,    // (7,32)
    const float* __restrict__ dom_table,    // (32,32)
    const float* __restrict__ doy_table,    // (367,64)
    float4* __restrict__ out)               // (B,T,V,D) as float4
{
    __shared__ __align__(16) float pos[DD];
    __shared__ float sx[VV];

    const int bt  = blockIdx.x;       // b*T + t
    const int b   = bt / TT;
    const int tid = threadIdx.x;

    // ---- build composite positional vector pos[0..255] in smem ----
    if (tid < 128) {
        const int tod = bar_in_day[bt];
        pos[tid] = tod_table[tod * 128 + tid];
    } else if (tid < 160) {
        pos[tid] = dow_table[day_of_week[b] * 32 + (tid - 128)];
    } else if (tid < 192) {
        pos[tid] = dom_table[day_of_month[b] * 32 + (tid - 160)];
    } else {
        pos[tid] = doy_table[day_of_year[b] * 64 + (tid - 192)];
    }
    if (tid < VV) sx[tid] = features[bt * VV + tid];
    __syncthreads();

    const float4* __restrict__ pos4 = reinterpret_cast<const float4*>(pos);
    float4* __restrict__ outb = out + (size_t)bt * (VV * DD / 4);

    // 24 rows of 64 float4 = 1536 float4 per block; 6 per thread.
    #pragma unroll
    for (int k = 0; k < 6; k++) {
        const int p  = tid + k * 256;   // 0..1535
        const int v  = p >> 6;          // uniform across each warp
        const int d4 = p & 63;
        const float  x  = sx[v];
        const float4 w  = W[v * 64 + d4];
        const float4 bv = bias[v * 64 + d4];
        const float4 pp = pos4[d4];
        float4 o;
        o.x = fmaf(x, w.x, bv.x) + pp.x;
        o.y = fmaf(x, w.y, bv.y) + pp.y;
        o.z = fmaf(x, w.z, bv.z) + pp.z;
        o.w = fmaf(x, w.w, bv.w) + pp.w;
        outb[p] = o;                    // default write-back store: let L2 buffer the stream
    }
}

extern "C" void kernel_launch(void* const* d_in, const int* in_sizes, int n_in,
                              void* d_out, int out_size) {
    const float* features     = (const float*)d_in[0];
    const int*   bar_in_day   = (const int*)d_in[1];
    const int*   day_of_week  = (const int*)d_in[2];
    const int*   day_of_month = (const int*)d_in[3];
    const int*   day_of_year  = (const int*)d_in[4];
    const float4* W           = (const float4*)d_in[5];
    const float4* bias        = (const float4*)d_in[6];
    const float* tod_table    = (const float*)d_in[7];
    const float* dow_table    = (const float*)d_in[8];
    const float* dom_table    = (const float*)d_in[9];
    const float* doy_table    = (const float*)d_in[10];
    float4* out = (float4*)d_out;

    input_embedding_kernel<<<BB * TT, 256>>>(
        features, bar_in_day, day_of_week, day_of_month, day_of_year,
        W, bias, tod_table, dow_table, dom_table, doy_table, out);
}